// round 6
// baseline (speedup 1.0000x reference)
#include <cuda_runtime.h>
#include <math.h>
#include <stdint.h>

// ---------------------------------------------------------------------------
// C=64 channels, 10x10x10 pixel-shuffle unfold -> M = 64000 rows.
// Branch dims: axi D=140 (w=5,7,4), cor D=112 (w=4,4,7), sag D=160 (w=4,8,5).
// atlas0: 64000 x 120 (w=5,6,4), shared across branches.
// Algebra:
//   G0 = atlas0^T B (120 x D);  G[i,j] = G0[colmap(i), j]
//   S = Wq^T G Wk + (Wq^T sA) bk^T + bq (sB^T Wk + M bk)^T,  sA[i]=s0[colmap(i)]
//   P = softmax_rows(S);  cross = B (Wv P^T) + 1 (P bv)^T   (scattered to out)
// B is never materialized: B[m,j] = g_pads[ccBase(m) + mterm(m) + jterm(j)]
// Tensor cores: mma.sync.m16n8k8.tf32, 3xTF32 (hi*hi + hi*lo + lo*hi).
// hi/lo splits PRECOMPUTED into float2 globals -> GEMM loaders are pure LDG.64.
// ---------------------------------------------------------------------------

#define NCH 5   // K-split chunks per channel in gemmG0 (200 rows each)

__device__ float2 g_atls[64000*120];   // atlas0 (hi,lo)
__device__ float2 g_pads[64000*160];   // padded transpose-folded feat (hi,lo)
__device__ float  g_G0p[NCH*120*160];  // split-K partial G0 slabs
__device__ float  g_G0[120*160];
__device__ float  g_T[160*160];
__device__ float  g_S[160*160];
__device__ float2 g_Us[160*160];       // U (hi,lo)
__device__ float  g_s0[120];
__device__ float  g_sB[160];
__device__ float  g_Z[160];
__device__ float  g_pb[160];

template<int BR> struct Cfg;
template<> struct Cfg<0>{
  static constexpr int D=140, W0=5,W1=7,W2=4, P0=1,P1=2,P2=1, I0=48,I1=66,I2=38;
  static constexpr int PS0=50,PS1=70,PS2=40, OUT0=0;
};
template<> struct Cfg<1>{
  static constexpr int D=112, W0=4,W1=4,W2=7, P0=1,P1=1,P2=2, I0=38,I1=38,I2=66;
  static constexpr int PS0=40,PS1=40,PS2=70, OUT0=7704576;
};
template<> struct Cfg<2>{
  static constexpr int D=160, W0=4,W1=8,W2=5, P0=1,P1=1,P2=1, I0=38,I1=78,I2=48;
  static constexpr int PS0=40,PS1=80,PS2=50, OUT0=13804032;
};

template<int BR>
__device__ __forceinline__ float loadFeat(const float* __restrict__ f, int cc, int z, int y, int x){
  if ((unsigned)z >= (unsigned)Cfg<BR>::I0 ||
      (unsigned)y >= (unsigned)Cfg<BR>::I1 ||
      (unsigned)x >= (unsigned)Cfg<BR>::I2) return 0.f;
  if constexpr (BR==0) return f[((cc*48+z)*66+y)*38+x];
  else if constexpr (BR==1) return f[((cc*38+z)*66+x)*38+y];
  else                      return f[((cc*48+x)*78+y)*38+z];
}

template<int BR>
__device__ __forceinline__ int outIndex(int cc, int z, int y, int x){
  if constexpr (BR==0) return ((cc*48+z)*66+y)*38+x;
  else if constexpr (BR==1) return Cfg<1>::OUT0 + ((cc*38+z)*66+x)*38+y;
  else                      return Cfg<2>::OUT0 + ((cc*48+x)*78+y)*38+z;
}

template<int BR>
__device__ __forceinline__ int atlasCol(int j){
  if constexpr (BR==0){
    int z=j/28, y=(j/4)%7, x=j%4;
    int y0=(y*6)/7;
    return (z*6+y0)*4+x;
  } else if constexpr (BR==1){
    int z=j/28, y=(j/7)%4, x=j%7;
    int z1=(z*5)/4, y1=(y*7)/4, x1=(x*4)/7;
    int y0=(y1*6)/7;
    return (z1*6+y0)*4+x1;
  } else {
    int z=j/40, y=(j/5)%8, x=j%5;
    int z2=z,  y2=y/2,     x2=(x*7)/5;
    int z1=(z2*5)/4, y1=(y2*7)/4, x1=(x2*4)/7;
    int y0=(y1*6)/7;
    return (z1*6+y0)*4+x1;
  }
}

// ---------------- tf32 helpers ----------------

__device__ __forceinline__ float2 splitf(float x){
  uint32_t u; asm("cvt.rna.tf32.f32 %0, %1;" : "=r"(u) : "f"(x));
  float hi = __uint_as_float(u);
  return make_float2(hi, x - hi);
}

__device__ __forceinline__ void mma_tf32(float c[4],
    uint32_t a0, uint32_t a1, uint32_t a2, uint32_t a3,
    uint32_t b0, uint32_t b1){
  asm volatile(
    "mma.sync.aligned.m16n8k8.row.col.f32.tf32.tf32.f32 "
    "{%0,%1,%2,%3}, {%4,%5,%6,%7}, {%8,%9}, {%0,%1,%2,%3};"
    : "+f"(c[0]), "+f"(c[1]), "+f"(c[2]), "+f"(c[3])
    : "r"(a0), "r"(a1), "r"(a2), "r"(a3), "r"(b0), "r"(b1));
}

// ---------------- kernels ----------------

__global__ void zero_small(){
  int t = blockIdx.x*256 + threadIdx.x;
  if (t < NCH*120*160) g_G0p[t] = 0.f;
  if (t < 120) g_s0[t]=0.f;
  if (t < 160) g_sB[t]=0.f;
}

__global__ void build_atlas0(const float* __restrict__ atlas){
  int idx = blockIdx.x*256 + threadIdx.x;
  if (idx >= 64000*120) return;
  int m = idx / 120, j = idx % 120;
  int cc = m / 1000, r = m % 1000;
  int a0 = r/100, a1 = (r/10)%10, a2 = r%10;
  int b0 = j/24, b1 = (j/4)%6, b2 = j%4;
  int z = a0*5 + b0 - 2, y = a1*6 + b1 - 2, x = a2*4 + b2 - 1;
  float v = 0.f;
  if ((unsigned)z < 46u && (unsigned)y < 56u && (unsigned)x < 38u)
    v = atlas[((cc*46+z)*56+y)*38+x];
  g_atls[idx] = splitf(v);
}

template<int BR>
__global__ void build_pad(const float* __restrict__ feat){
  constexpr int PS0=Cfg<BR>::PS0, PS1=Cfg<BR>::PS1, PS2=Cfg<BR>::PS2;
  int bz = blockIdx.x;
  int cc = bz / PS0, zp = bz % PS0;
  int z = zp - Cfg<BR>::P0;
  float2* dst = g_pads + (size_t)bz * (PS1*PS2);
  for (int i = threadIdx.x; i < PS1*PS2; i += blockDim.x){
    int yp = i / PS2, xp = i % PS2;
    dst[i] = splitf(loadFeat<BR>(feat, cc, z, yp - Cfg<BR>::P1, xp - Cfg<BR>::P2));
  }
}

// G0 = atlas0^T B (120 x D). 512 threads, M-tile 128 (covers all 120 rows),
// N-tile 64, k8 ping-pong. blockIdx.z = cc*NCH + chunk (200 rows).
// 16 warps as 4x4: warp tile 32x16 (2 mt x 2 nt of m16n8). 3xTF32.
template<int BR>
__global__ void __launch_bounds__(512,2) gemmG0(){
  constexpr int D=Cfg<BR>::D, W0=Cfg<BR>::W0, W1=Cfg<BR>::W1, W2=Cfg<BR>::W2;
  constexpr int S1=Cfg<BR>::PS1*Cfg<BR>::PS2, S2=Cfg<BR>::PS2;
  __shared__ float Ahi[2][8][136], Alo[2][8][136];
  __shared__ float Bhi[2][8][72],  Blo[2][8][72];
  __shared__ int mterm[200];
  __shared__ int jterm[64];
  int tj0 = blockIdx.x*64;
  int zc = blockIdx.z;
  int cc = zc / NCH, ch = zc % NCH;
  int r0 = ch*200;
  int t = threadIdx.x;

  if (t < 200){
    int r = r0 + t;
    int a0=r/100, a1=(r/10)%10, a2=r%10;
    mterm[t] = (a0*W0)*S1 + (a1*W1)*S2 + (a2*W2);
  }
  if (t >= 256 && t < 320){
    int lj = t - 256;
    int j = tj0 + lj;
    if (j < D){
      int b0=j/(W1*W2), b1=(j/W2)%W1, b2=j%W2;
      jterm[lj] = b0*S1 + b1*S2 + b2;
    } else jterm[lj] = 0;
  }
  __syncthreads();

  int lc  = t & 127, lr  = t >> 7;  // A loader: 128 cols x 4 row-groups (x2 k)
  int lcB = t & 63,  kkB = t >> 6;  // B loader: 64 cols x 8 k-rows
  bool aok = lc < 120;
  bool jok = (tj0 + lcB) < D;
  int jt = jterm[lcB];
  const float2* atl2 = g_atls + (size_t)cc*120000 + (size_t)r0*120 + lc;
  const float2* pad2 = g_pads + (size_t)cc*(1000*D);

  int wid = t >> 5, lane = t & 31;
  int wi = wid >> 2, wj = wid & 3;
  int group = lane >> 2, tig = lane & 3;

  float acc[2][2][4];
  #pragma unroll
  for (int a=0;a<2;a++)
    #pragma unroll
    for (int b=0;b<2;b++)
      #pragma unroll
      for (int q=0;q<4;q++) acc[a][b][q]=0.f;
  float aCS = 0.f, bCS = 0.f;

  auto loadTile = [&](int it, int p){
    #pragma unroll
    for (int s=0;s<2;s++){
      int kk = lr + 4*s;
      int r = it*8 + kk;
      float2 v = aok ? atl2[(size_t)r*120] : make_float2(0.f,0.f);
      Ahi[p][kk][lc] = v.x; Alo[p][kk][lc] = v.y;
      aCS += v.x + v.y;
    }
    {
      int r = it*8 + kkB;
      float2 w = jok ? pad2[mterm[r] + jt] : make_float2(0.f,0.f);
      Bhi[p][kkB][lcB] = w.x; Blo[p][kkB][lcB] = w.y;
      bCS += w.x + w.y;
    }
  };

  loadTile(0, 0);
  __syncthreads();
  int p = 0;
  for (int it = 0; it < 25; it++){
    if (it + 1 < 25) loadTile(it+1, p^1);
    uint32_t bH[2][2], bL[2][2];
    #pragma unroll
    for (int nt=0; nt<2; nt++){
      int cj = wj*16 + nt*8 + group;
      bH[nt][0] = __float_as_uint(Bhi[p][tig  ][cj]);
      bH[nt][1] = __float_as_uint(Bhi[p][tig+4][cj]);
      bL[nt][0] = __float_as_uint(Blo[p][tig  ][cj]);
      bL[nt][1] = __float_as_uint(Blo[p][tig+4][cj]);
    }
    #pragma unroll
    for (int mt=0; mt<2; mt++){
      int ri = wi*32 + mt*16 + group;
      uint32_t aH0 = __float_as_uint(Ahi[p][tig  ][ri]);
      uint32_t aH1 = __float_as_uint(Ahi[p][tig  ][ri+8]);
      uint32_t aH2 = __float_as_uint(Ahi[p][tig+4][ri]);
      uint32_t aH3 = __float_as_uint(Ahi[p][tig+4][ri+8]);
      uint32_t aL0 = __float_as_uint(Alo[p][tig  ][ri]);
      uint32_t aL1 = __float_as_uint(Alo[p][tig  ][ri+8]);
      uint32_t aL2 = __float_as_uint(Alo[p][tig+4][ri]);
      uint32_t aL3 = __float_as_uint(Alo[p][tig+4][ri+8]);
      #pragma unroll
      for (int nt=0; nt<2; nt++){
        mma_tf32(acc[mt][nt], aH0,aH1,aH2,aH3, bH[nt][0],bH[nt][1]);
        mma_tf32(acc[mt][nt], aH0,aH1,aH2,aH3, bL[nt][0],bL[nt][1]);
        mma_tf32(acc[mt][nt], aL0,aL1,aL2,aL3, bH[nt][0],bH[nt][1]);
      }
    }
    __syncthreads();
    p ^= 1;
  }

  float* slab = g_G0p + ch*(120*160);
  #pragma unroll
  for (int mt=0; mt<2; mt++){
    #pragma unroll
    for (int nt=0; nt<2; nt++){
      int i0 = wi*32 + mt*16 + group;
      int j0 = tj0 + wj*16 + nt*8 + tig*2;
      float* c = acc[mt][nt];
      if (i0 < 120){
        if (j0   < D) atomicAdd(&slab[i0*D + j0],   c[0]);
        if (j0+1 < D) atomicAdd(&slab[i0*D + j0+1], c[1]);
      }
      if (i0+8 < 120){
        if (j0   < D) atomicAdd(&slab[(i0+8)*D + j0],   c[2]);
        if (j0+1 < D) atomicAdd(&slab[(i0+8)*D + j0+1], c[3]);
      }
    }
  }
  if (blockIdx.x==0 && aok) atomicAdd(&g_s0[lc], aCS);
  if (jok) atomicAdd(&g_sB[tj0+lcB], bCS);
}

template<int D>
__global__ void reduceG0(){
  int idx = blockIdx.x*256 + threadIdx.x;
  if (idx >= 120*D) return;
  float s = 0.f;
  #pragma unroll
  for (int c=0;c<NCH;c++) s += g_G0p[c*(120*160) + idx];
  g_G0[idx] = s;
}

template<int BR>
__global__ void smallT(const float* __restrict__ Wk, const float* __restrict__ bk){
  constexpr int D = Cfg<BR>::D;
  int idx = blockIdx.x*256 + threadIdx.x;
  if (idx < D*D){
    int p = idx/D, j = idx%D;
    int gp = atlasCol<BR>(p);
    float acc = 0.f;
    for (int r=0;r<D;r++) acc += g_G0[gp*D+r]*Wk[r*D+j];
    g_T[idx] = acc;
  }
  if (idx < D){
    float z = 0.f;
    for (int r=0;r<D;r++) z += g_sB[r]*Wk[r*D+idx];
    g_Z[idx] = z + 64000.f*bk[idx];
  }
}

template<int BR>
__global__ void smallS(const float* __restrict__ Wq, const float* __restrict__ bq,
                       const float* __restrict__ bk){
  constexpr int D = Cfg<BR>::D;
  __shared__ float sAl[160];
  int t = threadIdx.x;
  if (t < D) sAl[t] = g_s0[atlasCol<BR>(t)];
  __syncthreads();
  int idx = blockIdx.x*256 + t;
  if (idx >= D*D) return;
  int i = idx/D, j = idx%D;
  float acc = 0.f, acc2 = 0.f;
  for (int p=0;p<D;p++){
    float w = Wq[p*D+i];
    acc  += w * g_T[p*D+j];
    acc2 += w * sAl[p];
  }
  g_S[idx] = acc + acc2*bk[j] + bq[i]*g_Z[j];
}

template<int D>
__global__ void softmaxK(){
  __shared__ float red[256];
  int i = blockIdx.x, t = threadIdx.x;
  float v = (t < D) ? g_S[i*D+t] : -3.4e38f;
  red[t] = v; __syncthreads();
  for (int s=128; s>0; s>>=1){ if (t<s) red[t]=fmaxf(red[t],red[t+s]); __syncthreads(); }
  float mx = red[0]; __syncthreads();
  float e = (t < D) ? expf(v - mx) : 0.f;
  red[t] = e; __syncthreads();
  for (int s=128; s>0; s>>=1){ if (t<s) red[t]+=red[t+s]; __syncthreads(); }
  float sum = red[0];
  if (t < D) g_S[i*D+t] = e / sum;
}

// U[r,i] = Wv[r,:].P[i,:]; stored pre-split. pb[i] = P[i,:].bv
template<int D>
__global__ void smallU(const float* __restrict__ Wv, const float* __restrict__ bv){
  int idx = blockIdx.x*256 + threadIdx.x;
  if (idx >= D*D) return;
  int rr = idx/D, i = idx%D;
  float acc = 0.f;
  for (int j=0;j<D;j++) acc += Wv[rr*D+j]*g_S[i*D+j];
  g_Us[idx] = splitf(acc);
  if (idx < D){
    float a = 0.f;
    for (int j=0;j<D;j++) a += g_S[idx*D+j]*bv[j];
    g_pb[idx] = a;
  }
}

// cross = Bm*U + pb. 512 threads, tile 128m x 64n, k8 ping-pong, 3xTF32.
// Scatter (fold + crop + inverse transpose) straight to out.
template<int BR>
__global__ void __launch_bounds__(512,2) crossK(float* __restrict__ out){
  constexpr int D=Cfg<BR>::D, W0=Cfg<BR>::W0, W1=Cfg<BR>::W1, W2=Cfg<BR>::W2;
  constexpr int S1=Cfg<BR>::PS1*Cfg<BR>::PS2, S2=Cfg<BR>::PS2;
  constexpr int KT = (D + 7) / 8;
  __shared__ float Ahi[2][8][136], Alo[2][8][136];
  __shared__ float Bhi[2][8][72],  Blo[2][8][72];
  __shared__ int mterm[128];
  __shared__ int jterm[160];
  int n0 = blockIdx.x*64, m0 = blockIdx.y*128;
  int t = threadIdx.x;

  if (t < 128){
    int m = m0 + t;
    int cc = m/1000, r = m%1000;
    int a0 = r/100, a1 = (r/10)%10, a2 = r%10;
    mterm[t] = cc*(1000*D) + (a0*W0)*S1 + (a1*W1)*S2 + (a2*W2);
  }
  if (t >= 256 && t < 256 + D){
    int j = t - 256;
    int b0=j/(W1*W2), b1=(j/W2)%W1, b2=j%W2;
    jterm[j] = b0*S1 + b1*S2 + b2;
  }
  __syncthreads();

  int lc  = t & 127, lr  = t >> 7;
  int lcB = t & 63,  kkB = t >> 6;
  int mt_ = mterm[lc];
  bool nok = (n0 + lcB) < D;

  int wid = t >> 5, lane = t & 31;
  int wi = wid >> 2, wj = wid & 3;
  int group = lane >> 2, tig = lane & 3;

  float acc[2][2][4];
  #pragma unroll
  for (int a=0;a<2;a++)
    #pragma unroll
    for (int b=0;b<2;b++)
      #pragma unroll
      for (int q=0;q<4;q++) acc[a][b][q]=0.f;

  auto loadTile = [&](int kc, int p){
    #pragma unroll
    for (int s=0;s<2;s++){
      int kk = lr + 4*s;
      int k = kc*8 + kk;
      float2 v = (k < D) ? g_pads[mt_ + jterm[k]] : make_float2(0.f,0.f);
      Ahi[p][kk][lc] = v.x; Alo[p][kk][lc] = v.y;
    }
    {
      int k = kc*8 + kkB;
      float2 w = (k < D && nok) ? g_Us[k*D + n0 + lcB] : make_float2(0.f,0.f);
      Bhi[p][kkB][lcB] = w.x; Blo[p][kkB][lcB] = w.y;
    }
  };

  loadTile(0, 0);
  __syncthreads();
  int p = 0;
  for (int kc=0; kc<KT; kc++){
    if (kc + 1 < KT) loadTile(kc+1, p^1);
    uint32_t bH[2][2], bL[2][2];
    #pragma unroll
    for (int nt=0; nt<2; nt++){
      int cj = wj*16 + nt*8 + group;
      bH[nt][0] = __float_as_uint(Bhi[p][tig  ][cj]);
      bH[nt][1] = __float_as_uint(Bhi[p][tig+4][cj]);
      bL[nt][0] = __float_as_uint(Blo[p][tig  ][cj]);
      bL[nt][1] = __float_as_uint(Blo[p][tig+4][cj]);
    }
    #pragma unroll
    for (int mt=0; mt<2; mt++){
      int ri = wi*32 + mt*16 + group;
      uint32_t aH0 = __float_as_uint(Ahi[p][tig  ][ri]);
      uint32_t aH1 = __float_as_uint(Ahi[p][tig  ][ri+8]);
      uint32_t aH2 = __float_as_uint(Ahi[p][tig+4][ri]);
      uint32_t aH3 = __float_as_uint(Ahi[p][tig+4][ri+8]);
      uint32_t aL0 = __float_as_uint(Alo[p][tig  ][ri]);
      uint32_t aL1 = __float_as_uint(Alo[p][tig  ][ri+8]);
      uint32_t aL2 = __float_as_uint(Alo[p][tig+4][ri]);
      uint32_t aL3 = __float_as_uint(Alo[p][tig+4][ri+8]);
      #pragma unroll
      for (int nt=0; nt<2; nt++){
        mma_tf32(acc[mt][nt], aH0,aH1,aH2,aH3, bH[nt][0],bH[nt][1]);
        mma_tf32(acc[mt][nt], aH0,aH1,aH2,aH3, bL[nt][0],bL[nt][1]);
        mma_tf32(acc[mt][nt], aL0,aL1,aL2,aL3, bH[nt][0],bH[nt][1]);
      }
    }
    __syncthreads();
    p ^= 1;
  }

  #pragma unroll
  for (int mt=0; mt<2; mt++){
    #pragma unroll
    for (int rr=0; rr<2; rr++){
      int m = m0 + wi*32 + mt*16 + rr*8 + group;
      int cc = m/1000, r = m%1000;
      int a0 = r/100, a1 = (r/10)%10, a2 = r%10;
      int zb = a0*W0 - Cfg<BR>::P0;
      int yb = a1*W1 - Cfg<BR>::P1;
      int xb = a2*W2 - Cfg<BR>::P2;
      #pragma unroll
      for (int nt=0; nt<2; nt++){
        int j0 = n0 + wj*16 + nt*8 + tig*2;
        #pragma unroll
        for (int jj=0; jj<2; jj++){
          int j = j0 + jj;
          if (j >= D) continue;
          int b0 = j/(W1*W2), b1 = (j/W2)%W1, b2 = j%W2;
          int z = zb + b0, y = yb + b1, x = xb + b2;
          if ((unsigned)z < (unsigned)Cfg<BR>::I0 &&
              (unsigned)y < (unsigned)Cfg<BR>::I1 &&
              (unsigned)x < (unsigned)Cfg<BR>::I2){
            out[outIndex<BR>(cc,z,y,x)] = acc[mt][nt][rr*2+jj] + g_pb[j];
          }
        }
      }
    }
  }
}

// ---------------- host orchestration ----------------

template<int BR>
static void runBranch(const float* feat, void* const* w, float* out){
  constexpr int D = Cfg<BR>::D;
  const float *Wq=(const float*)w[0], *bq=(const float*)w[1];
  const float *Wk=(const float*)w[2], *bk=(const float*)w[3];
  const float *Wv=(const float*)w[4], *bv=(const float*)w[5];

  zero_small<<<(NCH*120*160+255)/256, 256>>>();
  build_pad<BR><<<64*Cfg<BR>::PS0, 256>>>(feat);

  dim3 gg((D+63)/64, 1, 64*NCH);
  gemmG0<BR><<<gg, 512>>>();
  reduceG0<D><<<(120*D+255)/256, 256>>>();

  int nb = (D*D+255)/256;
  smallT<BR><<<nb, 256>>>(Wk, bk);
  smallS<BR><<<nb, 256>>>(Wq, bq, bk);
  softmaxK<D><<<D, 256>>>();
  smallU<D><<<nb, 256>>>(Wv, bv);

  dim3 gc((D+63)/64, 500);
  crossK<BR><<<gc, 512>>>(out);
}

extern "C" void kernel_launch(void* const* d_in, const int* in_sizes, int n_in,
                              void* d_out, int out_size){
  (void)in_sizes; (void)n_in; (void)out_size;
  const float* axi   = (const float*)d_in[0];
  const float* cor   = (const float*)d_in[1];
  const float* sag   = (const float*)d_in[2];
  const float* atlas = (const float*)d_in[3];
  float* out = (float*)d_out;

  build_atlas0<<<(64000*120+255)/256, 256>>>(atlas);

  runBranch<0>(axi, d_in + 4,  out);
  runBranch<1>(cor, d_in + 10, out);
  runBranch<2>(sag, d_in + 16, out);
}

// round 8
// speedup vs baseline: 1.2272x; 1.2272x over previous
#include <cuda_runtime.h>
#include <math.h>
#include <stdint.h>

// ---------------------------------------------------------------------------
// C=64 channels, 10x10x10 pixel-shuffle unfold -> M = 64000 rows.
// Branch dims: axi D=140 (w=5,7,4), cor D=112 (w=4,4,7), sag D=160 (w=4,8,5).
// atlas0: 64000 x 120 (w=5,6,4), shared across branches. Col 120 of g_atls is
// an all-ones column -> GEMM row 120 of G0 slabs = sB (column sums of B), free.
// Algebra:
//   G0 = atlas0^T B (121 x D incl. ones row);  G[i,j] = G0[colmap(i), j]
//   S = Wq^T G Wk + (Wq^T sA) bk^T + bq (sB^T Wk + M bk)^T,  sA[i]=s0[colmap(i)]
//   P = softmax_rows(S);  cross = B (Wv P^T) + 1 (P bv)^T   (scattered to out)
// B never materialized: B[m,j] = g_pads[ccBase(m) + mterm(m) + jterm(j)]
// Tensor cores: mma.sync.m16n8k8.tf32, 3xTF32 (hi*hi + hi*lo + lo*hi),
// fed by a 3-stage cp.async pipeline (gather latency hidden).
// ---------------------------------------------------------------------------

#define NCH 5   // K-split chunks per channel in gemmG0 (200 rows each)

__device__ float2 g_atls[64000*128];   // atlas0 (hi,lo); col120=ones, 121-127=0
__device__ float2 g_pads[64000*160];   // padded transpose-folded feat (hi,lo)
__device__ float  g_G0p[NCH*121*160];  // split-K partial G0 slabs (row 120 = sB)
__device__ float  g_G0[120*160];
__device__ float  g_T[160*160];
__device__ float  g_S[160*160];
__device__ float2 g_Us[160*160];       // U (hi,lo)
__device__ float  g_s0[120];
__device__ float  g_sB[160];
__device__ float  g_Z[160];
__device__ float  g_pb[160];

template<int BR> struct Cfg;
template<> struct Cfg<0>{
  static constexpr int D=140, W0=5,W1=7,W2=4, P0=1,P1=2,P2=1, I0=48,I1=66,I2=38;
  static constexpr int PS0=50,PS1=70,PS2=40, OUT0=0;
};
template<> struct Cfg<1>{
  static constexpr int D=112, W0=4,W1=4,W2=7, P0=1,P1=1,P2=2, I0=38,I1=38,I2=66;
  static constexpr int PS0=40,PS1=40,PS2=70, OUT0=7704576;
};
template<> struct Cfg<2>{
  static constexpr int D=160, W0=4,W1=8,W2=5, P0=1,P1=1,P2=1, I0=38,I1=78,I2=48;
  static constexpr int PS0=40,PS1=80,PS2=50, OUT0=13804032;
};

template<int BR>
__device__ __forceinline__ float loadFeat(const float* __restrict__ f, int cc, int z, int y, int x){
  if ((unsigned)z >= (unsigned)Cfg<BR>::I0 ||
      (unsigned)y >= (unsigned)Cfg<BR>::I1 ||
      (unsigned)x >= (unsigned)Cfg<BR>::I2) return 0.f;
  if constexpr (BR==0) return f[((cc*48+z)*66+y)*38+x];
  else if constexpr (BR==1) return f[((cc*38+z)*66+x)*38+y];
  else                      return f[((cc*48+x)*78+y)*38+z];
}

template<int BR>
__device__ __forceinline__ int outIndex(int cc, int z, int y, int x){
  if constexpr (BR==0) return ((cc*48+z)*66+y)*38+x;
  else if constexpr (BR==1) return Cfg<1>::OUT0 + ((cc*38+z)*66+x)*38+y;
  else                      return Cfg<2>::OUT0 + ((cc*48+x)*78+y)*38+z;
}

template<int BR>
__device__ __forceinline__ int atlasCol(int j){
  if constexpr (BR==0){
    int z=j/28, y=(j/4)%7, x=j%4;
    int y0=(y*6)/7;
    return (z*6+y0)*4+x;
  } else if constexpr (BR==1){
    int z=j/28, y=(j/7)%4, x=j%7;
    int z1=(z*5)/4, y1=(y*7)/4, x1=(x*4)/7;
    int y0=(y1*6)/7;
    return (z1*6+y0)*4+x1;
  } else {
    int z=j/40, y=(j/5)%8, x=j%5;
    int z2=z,  y2=y/2,     x2=(x*7)/5;
    int z1=(z2*5)/4, y1=(y2*7)/4, x1=(x2*4)/7;
    int y0=(y1*6)/7;
    return (z1*6+y0)*4+x1;
  }
}

// ---------------- helpers ----------------

__device__ __forceinline__ float2 splitf(float x){
  uint32_t u; asm("cvt.rna.tf32.f32 %0, %1;" : "=r"(u) : "f"(x));
  float hi = __uint_as_float(u);
  return make_float2(hi, x - hi);
}

__device__ __forceinline__ void mma_tf32(float c[4],
    uint32_t a0, uint32_t a1, uint32_t a2, uint32_t a3,
    uint32_t b0, uint32_t b1){
  asm volatile(
    "mma.sync.aligned.m16n8k8.row.col.f32.tf32.tf32.f32 "
    "{%0,%1,%2,%3}, {%4,%5,%6,%7}, {%8,%9}, {%0,%1,%2,%3};"
    : "+f"(c[0]), "+f"(c[1]), "+f"(c[2]), "+f"(c[3])
    : "r"(a0), "r"(a1), "r"(a2), "r"(a3), "r"(b0), "r"(b1));
}

__device__ __forceinline__ uint32_t sptr(const void* p){
  return (uint32_t)__cvta_generic_to_shared(p);
}
// 8-byte cp.async with zero-fill when sz==0
__device__ __forceinline__ void cpa8(uint32_t d, const void* s, int sz){
  asm volatile("cp.async.ca.shared.global [%0], [%1], 8, %2;"
               :: "r"(d), "l"(s), "r"(sz));
}
#define CP_COMMIT() asm volatile("cp.async.commit_group;")
#define CP_WAIT1()  asm volatile("cp.async.wait_group 1;")

// ---------------- kernels ----------------

__global__ void zeroS0(){
  if (threadIdx.x < 120) g_s0[threadIdx.x] = 0.f;
}

__global__ void zero_small(){
  int t = blockIdx.x*256 + threadIdx.x;
  if (t < NCH*121*160) g_G0p[t] = 0.f;
}

// grid 640 = cc*10 + a0; writes g_atls (128-col stride incl. ones col),
// accumulates s0 via smem reduction.
__global__ void build_atlas0(const float* __restrict__ atlas){
  __shared__ float s0l[120];
  int t = threadIdx.x;
  if (t < 120) s0l[t] = 0.f;
  __syncthreads();
  int cc = blockIdx.x / 10, a0 = blockIdx.x % 10;
  int mBase = cc*1000 + a0*100;
  for (int e = t; e < 12000; e += 256){
    int sub = e / 120, j = e % 120;
    int a1 = sub/10, a2 = sub%10;
    int b0 = j/24, b1 = (j/4)%6, b2 = j%4;
    int z = a0*5+b0-2, y = a1*6+b1-2, x = a2*4+b2-1;
    float v = 0.f;
    if ((unsigned)z < 46u && (unsigned)y < 56u && (unsigned)x < 38u)
      v = atlas[((cc*46+z)*56+y)*38+x];
    g_atls[(size_t)(mBase+sub)*128 + j] = splitf(v);
    atomicAdd(&s0l[j], v);
  }
  for (int e = t; e < 800; e += 256){
    int rsub = e >> 3, col = 120 + (e & 7);
    g_atls[(size_t)(mBase+rsub)*128 + col] = make_float2(col==120 ? 1.f : 0.f, 0.f);
  }
  __syncthreads();
  if (t < 120) atomicAdd(&g_s0[t], s0l[t]);
}

template<int BR>
__global__ void build_pad(const float* __restrict__ feat){
  constexpr int PS0=Cfg<BR>::PS0, PS1=Cfg<BR>::PS1, PS2=Cfg<BR>::PS2;
  int bz = blockIdx.x;
  int cc = bz / PS0, zp = bz % PS0;
  int z = zp - Cfg<BR>::P0;
  float2* dst = g_pads + (size_t)bz * (PS1*PS2);
  for (int i = threadIdx.x; i < PS1*PS2; i += blockDim.x){
    int yp = i / PS2, xp = i % PS2;
    dst[i] = splitf(loadFeat<BR>(feat, cc, z, yp - Cfg<BR>::P1, xp - Cfg<BR>::P2));
  }
}

// G0 = atlas0^T B (121 x D incl ones-row=sB). 256 thr, M-tile 128, N-tile 64,
// k8, 3-stage cp.async, 3xTF32 mma. blockIdx.z = cc*NCH + chunk (200 rows).
template<int BR>
__global__ void __launch_bounds__(256,3) gemmG0(){
  constexpr int D=Cfg<BR>::D, W0=Cfg<BR>::W0, W1=Cfg<BR>::W1, W2=Cfg<BR>::W2;
  constexpr int S1=Cfg<BR>::PS1*Cfg<BR>::PS2, S2=Cfg<BR>::PS2;
  __shared__ float2 As[3][8][132];
  __shared__ float2 Bs[3][8][68];
  __shared__ int mterm[200];
  __shared__ int jterm[64];
  int tj0 = blockIdx.x*64;
  int zc = blockIdx.z, cc = zc/NCH, ch = zc%NCH, r0 = ch*200;
  int t = threadIdx.x;

  if (t < 200){
    int r = r0 + t;
    int a0=r/100, a1=(r/10)%10, a2=r%10;
    mterm[t] = (a0*W0)*S1 + (a1*W1)*S2 + (a2*W2);
  }
  if (t < 64){
    int j = tj0 + t;
    jterm[t] = (j < D) ? (j/(W1*W2))*S1 + ((j/W2)%W1)*S2 + (j%W2) : 0;
  }
  __syncthreads();

  int lc = t & 127, ka = t >> 7;   // A loader: 128 cols x 2 k-rows (x4)
  int lcB = t & 63, kb = t >> 6;   // B loader: 64 cols x 4 k-rows (x2)
  int szB = ((tj0 + lcB) < D) ? 8 : 0;
  const float2* atl  = g_atls + (size_t)(cc*1000 + r0)*128 + lc;
  const float2* padc = g_pads + (size_t)cc*(1000*D) + jterm[lcB];

  auto loadTile = [&](int it, int buf){
    #pragma unroll
    for (int s=0;s<4;s++){
      int kk = ka + 2*s;
      cpa8(sptr(&As[buf][kk][lc]), atl + (size_t)(it*8+kk)*128, 8);
    }
    #pragma unroll
    for (int s=0;s<2;s++){
      int kk = kb + 4*s;
      cpa8(sptr(&Bs[buf][kk][lcB]), padc + mterm[it*8+kk], szB);
    }
  };

  int wid=t>>5, lane=t&31, wi=wid>>2, wj=wid&3;
  int group=lane>>2, tig=lane&3;
  float acc[4][2][4];
  #pragma unroll
  for (int a=0;a<4;a++)
    #pragma unroll
    for (int b=0;b<2;b++)
      #pragma unroll
      for (int q=0;q<4;q++) acc[a][b][q]=0.f;

  loadTile(0,0); CP_COMMIT();
  loadTile(1,1); CP_COMMIT();
  CP_WAIT1(); __syncthreads();

  for (int it=0; it<25; it++){
    int buf = it % 3;
    uint32_t bH[2][2], bL[2][2];
    #pragma unroll
    for (int nt=0; nt<2; nt++){
      int cj = wj*16 + nt*8 + group;
      float2 b0 = Bs[buf][tig][cj];
      float2 b1 = Bs[buf][tig+4][cj];
      bH[nt][0]=__float_as_uint(b0.x); bL[nt][0]=__float_as_uint(b0.y);
      bH[nt][1]=__float_as_uint(b1.x); bL[nt][1]=__float_as_uint(b1.y);
    }
    #pragma unroll
    for (int mt=0; mt<4; mt++){
      int ri = wi*64 + mt*16 + group;
      float2 a00 = As[buf][tig][ri],   a01 = As[buf][tig][ri+8];
      float2 a10 = As[buf][tig+4][ri], a11 = As[buf][tig+4][ri+8];
      uint32_t aH0=__float_as_uint(a00.x), aH1=__float_as_uint(a01.x),
               aH2=__float_as_uint(a10.x), aH3=__float_as_uint(a11.x);
      uint32_t aL0=__float_as_uint(a00.y), aL1=__float_as_uint(a01.y),
               aL2=__float_as_uint(a10.y), aL3=__float_as_uint(a11.y);
      #pragma unroll
      for (int nt=0; nt<2; nt++){
        mma_tf32(acc[mt][nt], aH0,aH1,aH2,aH3, bH[nt][0],bH[nt][1]);
        mma_tf32(acc[mt][nt], aH0,aH1,aH2,aH3, bL[nt][0],bL[nt][1]);
        mma_tf32(acc[mt][nt], aL0,aL1,aL2,aL3, bH[nt][0],bH[nt][1]);
      }
    }
    int nx = it + 2;
    if (nx < 25) loadTile(nx, nx % 3);
    CP_COMMIT();
    CP_WAIT1();
    __syncthreads();
  }

  float* slab = g_G0p + ch*(121*160);
  #pragma unroll
  for (int mt=0; mt<4; mt++){
    #pragma unroll
    for (int nt=0; nt<2; nt++){
      int i0 = wi*64 + mt*16 + group;
      int j0 = tj0 + wj*16 + nt*8 + tig*2;
      float* c = acc[mt][nt];
      if (i0 <= 120){
        if (j0   < D) atomicAdd(&slab[i0*D + j0],   c[0]);
        if (j0+1 < D) atomicAdd(&slab[i0*D + j0+1], c[1]);
      }
      if (i0+8 <= 120){
        if (j0   < D) atomicAdd(&slab[(i0+8)*D + j0],   c[2]);
        if (j0+1 < D) atomicAdd(&slab[(i0+8)*D + j0+1], c[3]);
      }
    }
  }
}

// sum NCH partial slabs; rows 0..119 -> g_G0, row 120 -> g_sB
template<int D>
__global__ void reduceG0(){
  int idx = blockIdx.x*256 + threadIdx.x;
  if (idx >= 121*D) return;
  float s = 0.f;
  #pragma unroll
  for (int c=0;c<NCH;c++) s += g_G0p[c*(121*160) + idx];
  int i = idx / D, j = idx - i*D;
  if (i < 120) g_G0[idx] = s;
  else         g_sB[j] = s;
}

template<int BR>
__global__ void smallT(const float* __restrict__ Wk, const float* __restrict__ bk){
  constexpr int D = Cfg<BR>::D;
  int idx = blockIdx.x*256 + threadIdx.x;
  if (idx < D*D){
    int p = idx/D, j = idx%D;
    int gp = atlasCol<BR>(p);
    float acc = 0.f;
    for (int r=0;r<D;r++) acc += g_G0[gp*D+r]*Wk[r*D+j];
    g_T[idx] = acc;
  }
  if (idx < D){
    float z = 0.f;
    for (int r=0;r<D;r++) z += g_sB[r]*Wk[r*D+idx];
    g_Z[idx] = z + 64000.f*bk[idx];
  }
}

template<int BR>
__global__ void smallS(const float* __restrict__ Wq, const float* __restrict__ bq,
                       const float* __restrict__ bk){
  constexpr int D = Cfg<BR>::D;
  __shared__ float sAl[160];
  int t = threadIdx.x;
  if (t < D) sAl[t] = g_s0[atlasCol<BR>(t)];
  __syncthreads();
  int idx = blockIdx.x*256 + t;
  if (idx >= D*D) return;
  int i = idx/D, j = idx%D;
  float acc = 0.f, acc2 = 0.f;
  for (int p=0;p<D;p++){
    float w = Wq[p*D+i];
    acc  += w * g_T[p*D+j];
    acc2 += w * sAl[p];
  }
  g_S[idx] = acc + acc2*bk[j] + bq[i]*g_Z[j];
}

template<int D>
__global__ void softmaxK(){
  __shared__ float red[256];
  int i = blockIdx.x, t = threadIdx.x;
  float v = (t < D) ? g_S[i*D+t] : -3.4e38f;
  red[t] = v; __syncthreads();
  for (int s=128; s>0; s>>=1){ if (t<s) red[t]=fmaxf(red[t],red[t+s]); __syncthreads(); }
  float mx = red[0]; __syncthreads();
  float e = (t < D) ? expf(v - mx) : 0.f;
  red[t] = e; __syncthreads();
  for (int s=128; s>0; s>>=1){ if (t<s) red[t]+=red[t+s]; __syncthreads(); }
  float sum = red[0];
  if (t < D) g_S[i*D+t] = e / sum;
}

template<int D>
__global__ void smallU(const float* __restrict__ Wv, const float* __restrict__ bv){
  int idx = blockIdx.x*256 + threadIdx.x;
  if (idx >= D*D) return;
  int rr = idx/D, i = idx%D;
  float acc = 0.f;
  for (int j=0;j<D;j++) acc += Wv[rr*D+j]*g_S[i*D+j];
  g_Us[idx] = splitf(acc);
  if (idx < D){
    float a = 0.f;
    for (int j=0;j<D;j++) a += g_S[idx*D+j]*bv[j];
    g_pb[idx] = a;
  }
}

// cross = Bm*U + pb. 256 thr, tile 128m x 64n, k8, 3-stage cp.async, 3xTF32.
// Scatter (fold + crop + inverse transpose) straight to out.
template<int BR>
__global__ void __launch_bounds__(256,3) crossK(float* __restrict__ out){
  constexpr int D=Cfg<BR>::D, W0=Cfg<BR>::W0, W1=Cfg<BR>::W1, W2=Cfg<BR>::W2;
  constexpr int S1=Cfg<BR>::PS1*Cfg<BR>::PS2, S2=Cfg<BR>::PS2;
  constexpr int KT = (D + 7) / 8;
  __shared__ float2 As[3][8][132];
  __shared__ float2 Bs[3][8][68];
  __shared__ int mterm[128];
  __shared__ int jterm[160];
  int n0 = blockIdx.x*64, m0 = blockIdx.y*128;
  int t = threadIdx.x;

  if (t < 128){
    int m = m0 + t;
    int cc = m/1000, r = m%1000;
    int a0 = r/100, a1 = (r/10)%10, a2 = r%10;
    mterm[t] = cc*(1000*D) + (a0*W0)*S1 + (a1*W1)*S2 + (a2*W2);
  }
  if (t < 160)
    jterm[t] = (t < D) ? (t/(W1*W2))*S1 + ((t/W2)%W1)*S2 + (t%W2) : 0;
  __syncthreads();

  int lc = t & 127, ka = t >> 7;
  int lcB = t & 63, kb = t >> 6;
  int mt_ = mterm[lc];
  bool nok = (n0 + lcB) < D;

  auto loadTile = [&](int it, int buf){
    #pragma unroll
    for (int s=0;s<4;s++){
      int kk = ka + 2*s;
      int k = it*8 + kk;
      int sz = (k < D) ? 8 : 0;
      cpa8(sptr(&As[buf][kk][lc]), g_pads + mt_ + jterm[k], sz);
    }
    #pragma unroll
    for (int s=0;s<2;s++){
      int kk = kb + 4*s;
      int k = it*8 + kk;
      int sz = (k < D && nok) ? 8 : 0;
      cpa8(sptr(&Bs[buf][kk][lcB]), g_Us + k*D + n0 + lcB, sz);
    }
  };

  int wid=t>>5, lane=t&31, wi=wid>>2, wj=wid&3;
  int group=lane>>2, tig=lane&3;
  float acc[4][2][4];
  #pragma unroll
  for (int a=0;a<4;a++)
    #pragma unroll
    for (int b=0;b<2;b++)
      #pragma unroll
      for (int q=0;q<4;q++) acc[a][b][q]=0.f;

  loadTile(0,0); CP_COMMIT();
  loadTile(1,1); CP_COMMIT();
  CP_WAIT1(); __syncthreads();

  for (int kc=0; kc<KT; kc++){
    int buf = kc % 3;
    uint32_t bH[2][2], bL[2][2];
    #pragma unroll
    for (int nt=0; nt<2; nt++){
      int cj = wj*16 + nt*8 + group;
      float2 b0 = Bs[buf][tig][cj];
      float2 b1 = Bs[buf][tig+4][cj];
      bH[nt][0]=__float_as_uint(b0.x); bL[nt][0]=__float_as_uint(b0.y);
      bH[nt][1]=__float_as_uint(b1.x); bL[nt][1]=__float_as_uint(b1.y);
    }
    #pragma unroll
    for (int mt=0; mt<4; mt++){
      int ri = wi*64 + mt*16 + group;
      float2 a00 = As[buf][tig][ri],   a01 = As[buf][tig][ri+8];
      float2 a10 = As[buf][tig+4][ri], a11 = As[buf][tig+4][ri+8];
      uint32_t aH0=__float_as_uint(a00.x), aH1=__float_as_uint(a01.x),
               aH2=__float_as_uint(a10.x), aH3=__float_as_uint(a11.x);
      uint32_t aL0=__float_as_uint(a00.y), aL1=__float_as_uint(a01.y),
               aL2=__float_as_uint(a10.y), aL3=__float_as_uint(a11.y);
      #pragma unroll
      for (int nt=0; nt<2; nt++){
        mma_tf32(acc[mt][nt], aH0,aH1,aH2,aH3, bH[nt][0],bH[nt][1]);
        mma_tf32(acc[mt][nt], aH0,aH1,aH2,aH3, bL[nt][0],bL[nt][1]);
        mma_tf32(acc[mt][nt], aL0,aL1,aL2,aL3, bH[nt][0],bH[nt][1]);
      }
    }
    int nx = kc + 2;
    if (nx < KT) loadTile(nx, nx % 3);
    CP_COMMIT();
    CP_WAIT1();
    __syncthreads();
  }

  #pragma unroll
  for (int mt=0; mt<4; mt++){
    #pragma unroll
    for (int rr=0; rr<2; rr++){
      int m = m0 + wi*64 + mt*16 + rr*8 + group;
      int cc = m/1000, r = m%1000;
      int a0 = r/100, a1 = (r/10)%10, a2 = r%10;
      int zb = a0*W0 - Cfg<BR>::P0;
      int yb = a1*W1 - Cfg<BR>::P1;
      int xb = a2*W2 - Cfg<BR>::P2;
      #pragma unroll
      for (int nt=0; nt<2; nt++){
        int j0 = n0 + wj*16 + nt*8 + tig*2;
        #pragma unroll
        for (int jj=0; jj<2; jj++){
          int j = j0 + jj;
          if (j >= D) continue;
          int b0 = j/(W1*W2), b1 = (j/W2)%W1, b2 = j%W2;
          int z = zb + b0, y = yb + b1, x = xb + b2;
          if ((unsigned)z < (unsigned)Cfg<BR>::I0 &&
              (unsigned)y < (unsigned)Cfg<BR>::I1 &&
              (unsigned)x < (unsigned)Cfg<BR>::I2){
            out[outIndex<BR>(cc,z,y,x)] = acc[mt][nt][rr*2+jj] + g_pb[j];
          }
        }
      }
    }
  }
}

// ---------------- host orchestration ----------------

template<int BR>
static void runBranch(const float* feat, void* const* w, float* out){
  constexpr int D = Cfg<BR>::D;
  const float *Wq=(const float*)w[0], *bq=(const float*)w[1];
  const float *Wk=(const float*)w[2], *bk=(const float*)w[3];
  const float *Wv=(const float*)w[4], *bv=(const float*)w[5];

  zero_small<<<(NCH*121*160+255)/256, 256>>>();
  build_pad<BR><<<64*Cfg<BR>::PS0, 256>>>(feat);

  dim3 gg((D+63)/64, 1, 64*NCH);
  gemmG0<BR><<<gg, 256>>>();
  reduceG0<D><<<(121*D+255)/256, 256>>>();

  int nb = (D*D+255)/256;
  smallT<BR><<<nb, 256>>>(Wk, bk);
  smallS<BR><<<nb, 256>>>(Wq, bq, bk);
  softmaxK<D><<<D, 256>>>();
  smallU<D><<<nb, 256>>>(Wv, bv);

  dim3 gc((D+63)/64, 500);
  crossK<BR><<<gc, 256>>>(out);
}

extern "C" void kernel_launch(void* const* d_in, const int* in_sizes, int n_in,
                              void* d_out, int out_size){
  (void)in_sizes; (void)n_in; (void)out_size;
  const float* axi   = (const float*)d_in[0];
  const float* cor   = (const float*)d_in[1];
  const float* sag   = (const float*)d_in[2];
  const float* atlas = (const float*)d_in[3];
  float* out = (float*)d_out;

  zeroS0<<<1, 128>>>();
  build_atlas0<<<640, 256>>>(atlas);

  runBranch<0>(axi, d_in + 4,  out);
  runBranch<1>(cor, d_in + 10, out);
  runBranch<2>(sag, d_in + 16, out);
}